// round 5
// baseline (speedup 1.0000x reference)
#include <cuda_runtime.h>
#include <math.h>

#define NN     50000
#define EE     800000
#define ETMAX  (EE + NN)
#define INC    128
#define HEADS  3
#define HID    64
#define H1DIM  (HEADS * HID) // 192
#define OUTC   64

#define NEG_SLOPE 0.2f
#define EPSF 1e-16f

// ---------------- scratch (static device globals; no allocations) -------------
__device__ float  g_aggx[(size_t)NN * HEADS * INC]; // per-head aggregated x (76.8MB)
__device__ float  g_out1[(size_t)NN * H1DIM];       // layer1 output (post ELU)
__device__ float  g_h2  [(size_t)NN * OUTC];        // out1 @ W2
__device__ float  g_ws1 [2 * HEADS * INC];          // [sd][h][k] folded att vectors
__device__ float4 g_s1  [NN];                       // packed (as0,as1,as2,_) per node
__device__ float4 g_d1  [NN];                       // packed (ad0,ad1,ad2,_) per node
__device__ float  g_as2 [NN];
__device__ float  g_ad2 [NN];
__device__ int    g_deg   [NN];
__device__ int    g_cursor[NN];
__device__ int    g_off   [NN + 1];
__device__ int    g_elist [ETMAX];

// ---------------- CSR build ---------------------------------------------------
__global__ void k_init(int* __restrict__ deg, int* __restrict__ cur, int n) {
    int i = blockIdx.x * blockDim.x + threadIdx.x;
    if (i < n) { deg[i] = 0; cur[i] = 0; }
}

__global__ void k_hist(const int* __restrict__ ei, int* __restrict__ deg,
                       int e_real, int et) {
    int i = blockIdx.x * blockDim.x + threadIdx.x;
    if (i >= et) return;
    int dst = (i < e_real) ? ei[e_real + i] : (i - e_real);
    atomicAdd(&deg[dst], 1);
}

__global__ void k_scan(const int* __restrict__ deg, int* __restrict__ off, int n) {
    __shared__ int part[1024];
    int t = threadIdx.x;
    int chunk = (n + 1023) / 1024;
    int b = t * chunk;
    int s = 0;
    for (int j = 0; j < chunk; j++) { int idx = b + j; if (idx < n) s += deg[idx]; }
    part[t] = s;
    __syncthreads();
    for (int d = 1; d < 1024; d <<= 1) {
        int v = (t >= d) ? part[t - d] : 0;
        __syncthreads();
        part[t] += v;
        __syncthreads();
    }
    int run = (t == 0) ? 0 : part[t - 1];
    for (int j = 0; j < chunk; j++) {
        int idx = b + j;
        if (idx < n) { off[idx] = run; run += deg[idx]; }
    }
    if (t == 1023) off[n] = part[1023];
}

__global__ void k_bucket(const int* __restrict__ ei, const int* __restrict__ off,
                         int* __restrict__ cur, int* __restrict__ elist,
                         int e_real, int et) {
    int i = blockIdx.x * blockDim.x + threadIdx.x;
    if (i >= et) return;
    int src, dst;
    if (i < e_real) { src = ei[i]; dst = ei[e_real + i]; }
    else            { src = i - e_real; dst = src; }
    int pos = atomicAdd(&cur[dst], 1);
    elist[off[dst] + pos] = src;
}

// ---------------- fold att vectors through W1: ws[sd][h][k] -------------------
__global__ void k_wvec(const float* __restrict__ W1,
                       const float* __restrict__ att_s, const float* __restrict__ att_d,
                       float* __restrict__ ws) {
    int i = blockIdx.x * blockDim.x + threadIdx.x;   // 0..767
    if (i >= 2 * HEADS * INC) return;
    int sd = i / (HEADS * INC);
    int h  = (i / INC) % HEADS;
    int k  = i % INC;
    const float* att = sd ? att_d : att_s;
    float sum = 0.f;
    const float* wrow = &W1[(size_t)k * H1DIM + h * HID];
    const float* arow = &att[h * HID];
    #pragma unroll 8
    for (int c = 0; c < HID; c++) sum += wrow[c] * arow[c];
    ws[i] = sum;
}

// ---------------- per-node logits via GEMV on x (warp per node) ---------------
__global__ void k_logits(const float* __restrict__ x, const float* __restrict__ ws,
                         float4* __restrict__ s1, float4* __restrict__ d1, int n) {
    __shared__ float w[2 * HEADS * INC];
    for (int i = threadIdx.x; i < 2 * HEADS * INC; i += blockDim.x) w[i] = ws[i];
    __syncthreads();
    int node = blockIdx.x * (blockDim.x / 32) + (threadIdx.x >> 5);
    int lane = threadIdx.x & 31;
    if (node >= n) return;
    float4 xv = ((const float4*)(x + (size_t)node * INC))[lane];
    float r[6];
    #pragma unroll
    for (int j = 0; j < 6; j++) {
        const float* wv = &w[j * INC + lane * 4];
        r[j] = xv.x * wv[0] + xv.y * wv[1] + xv.z * wv[2] + xv.w * wv[3];
    }
    #pragma unroll
    for (int o = 16; o > 0; o >>= 1)
        #pragma unroll
        for (int j = 0; j < 6; j++) r[j] += __shfl_down_sync(0xffffffff, r[j], o);
    if (lane == 0) {
        s1[node] = make_float4(r[0], r[1], r[2], 0.f);
        d1[node] = make_float4(r[3], r[4], r[5], 0.f);
    }
}

// ---------------- layer-1 aggregation on x (warp per dst) ---------------------
// agg[dst][h][0:128] = sum_src alpha_h(src,dst) * x[src]
__global__ void k_gat1x(const int* __restrict__ elist, const int* __restrict__ off,
                        const float4* __restrict__ s1, const float4* __restrict__ d1,
                        const float* __restrict__ x, float* __restrict__ agg, int n) {
    int dst = blockIdx.x * (blockDim.x / 32) + (threadIdx.x >> 5);
    int lane = threadIdx.x & 31;
    if (dst >= n) return;
    int beg = off[dst], end = off[dst + 1];
    float4 ad = d1[dst];

    // pass 1: online softmax stats per head
    float m[3] = {-INFINITY, -INFINITY, -INFINITY};
    float s[3] = {0.f, 0.f, 0.f};
    for (int i = beg + lane; i < end; i += 32) {
        int src = elist[i];
        float4 as = s1[src];
        float e[3];
        e[0] = as.x + ad.x; e[1] = as.y + ad.y; e[2] = as.z + ad.z;
        #pragma unroll
        for (int h = 0; h < 3; h++) {
            float v = (e[h] > 0.f) ? e[h] : NEG_SLOPE * e[h];
            float nm = fmaxf(m[h], v);
            s[h] = s[h] * __expf(m[h] - nm) + __expf(v - nm);
            m[h] = nm;
        }
    }
    #pragma unroll
    for (int o = 16; o > 0; o >>= 1) {
        #pragma unroll
        for (int h = 0; h < 3; h++) {
            float m2 = __shfl_xor_sync(0xffffffff, m[h], o);
            float s2 = __shfl_xor_sync(0xffffffff, s[h], o);
            float nm = fmaxf(m[h], m2);
            float w1 = (m[h] == -INFINITY) ? 0.f : __expf(m[h] - nm);
            float w2 = (m2   == -INFINITY) ? 0.f : __expf(m2 - nm);
            s[h] = s[h] * w1 + s2 * w2;
            m[h] = nm;
        }
    }
    float inv[3];
    #pragma unroll
    for (int h = 0; h < 3; h++) inv[h] = 1.0f / (s[h] + EPSF);

    // pass 2: gather x rows, accumulate per head (4 ch/lane/head)
    float a0x=0,a0y=0,a0z=0,a0w=0, a1x=0,a1y=0,a1z=0,a1w=0, a2x=0,a2y=0,a2z=0,a2w=0;
    for (int i = beg; i < end; i++) {
        int src = elist[i];                 // uniform across warp
        float4 as = s1[src];
        float e0 = as.x + ad.x, e1 = as.y + ad.y, e2 = as.z + ad.z;
        e0 = (e0 > 0.f) ? e0 : NEG_SLOPE * e0;
        e1 = (e1 > 0.f) ? e1 : NEG_SLOPE * e1;
        e2 = (e2 > 0.f) ? e2 : NEG_SLOPE * e2;
        float al0 = __expf(e0 - m[0]) * inv[0];
        float al1 = __expf(e1 - m[1]) * inv[1];
        float al2 = __expf(e2 - m[2]) * inv[2];
        float4 xv = ((const float4*)(x + (size_t)src * INC))[lane];
        a0x = fmaf(xv.x, al0, a0x); a0y = fmaf(xv.y, al0, a0y);
        a0z = fmaf(xv.z, al0, a0z); a0w = fmaf(xv.w, al0, a0w);
        a1x = fmaf(xv.x, al1, a1x); a1y = fmaf(xv.y, al1, a1y);
        a1z = fmaf(xv.z, al1, a1z); a1w = fmaf(xv.w, al1, a1w);
        a2x = fmaf(xv.x, al2, a2x); a2y = fmaf(xv.y, al2, a2y);
        a2z = fmaf(xv.z, al2, a2z); a2w = fmaf(xv.w, al2, a2w);
    }
    float* op = &agg[(size_t)dst * (HEADS * INC)];
    ((float4*)op)[lane]                 = make_float4(a0x, a0y, a0z, a0w);
    ((float4*)(op + INC))[lane]         = make_float4(a1x, a1y, a1z, a1w);
    ((float4*)(op + 2 * INC))[lane]     = make_float4(a2x, a2y, a2z, a2w);
}

// ---------------- layer-1 GEMM per head with fused bias+ELU -------------------
// C[:, h*64:(h+1)*64] = ELU(agg[:, h, :] @ W1[:, h*64:...] + b1[h*64:...])
// BM=128, BN=64, BK=16, 256 threads, 8x4/thread.
__global__ void k_gemm_l1(const float* __restrict__ A0, const float* __restrict__ B0,
                          const float* __restrict__ bias, float* __restrict__ C0, int M) {
    __shared__ float As[16][129];
    __shared__ float Bs[16][68];

    int h = blockIdx.z;
    const float* A = A0 + h * INC;         // lda = 384
    const float* B = B0 + h * HID;         // ldb = 192
    float* C = C0 + h * HID;               // ldc = 192
    const float* bb = bias + h * HID;

    int tid = threadIdx.x;
    int tx = tid & 15, ty = tid >> 4;
    int m0 = blockIdx.y * 128;

    float acc[8][4];
    #pragma unroll
    for (int i = 0; i < 8; i++)
        #pragma unroll
        for (int j = 0; j < 4; j++) acc[i][j] = 0.0f;

    for (int k0 = 0; k0 < INC; k0 += 16) {
        #pragma unroll
        for (int q = 0; q < 2; q++) {
            int slot = tid + q * 256;
            int row = slot >> 2, kq = slot & 3;
            int gm = m0 + row;
            float4 v = make_float4(0.f, 0.f, 0.f, 0.f);
            if (gm < M) v = *(const float4*)&A[(size_t)gm * (HEADS * INC) + k0 + kq * 4];
            As[kq * 4 + 0][row] = v.x;
            As[kq * 4 + 1][row] = v.y;
            As[kq * 4 + 2][row] = v.z;
            As[kq * 4 + 3][row] = v.w;
        }
        {
            int kk = tid >> 4, col4 = (tid & 15) * 4;
            float4 v = *(const float4*)&B[(size_t)(k0 + kk) * H1DIM + col4];
            Bs[kk][col4 + 0] = v.x; Bs[kk][col4 + 1] = v.y;
            Bs[kk][col4 + 2] = v.z; Bs[kk][col4 + 3] = v.w;
        }
        __syncthreads();

        #pragma unroll
        for (int kk = 0; kk < 16; kk++) {
            float a[8], b[4];
            #pragma unroll
            for (int i = 0; i < 8; i++) a[i] = As[kk][ty * 8 + i];
            #pragma unroll
            for (int j = 0; j < 4; j++) b[j] = Bs[kk][tx * 4 + j];
            #pragma unroll
            for (int i = 0; i < 8; i++)
                #pragma unroll
                for (int j = 0; j < 4; j++) acc[i][j] = fmaf(a[i], b[j], acc[i][j]);
        }
        __syncthreads();
    }

    float b4[4];
    #pragma unroll
    for (int j = 0; j < 4; j++) b4[j] = bb[tx * 4 + j];

    #pragma unroll
    for (int i = 0; i < 8; i++) {
        int gm = m0 + ty * 8 + i;
        if (gm >= M) continue;
        float4 v;
        float t0 = acc[i][0] + b4[0]; v.x = (t0 > 0.f) ? t0 : expm1f(t0);
        float t1 = acc[i][1] + b4[1]; v.y = (t1 > 0.f) ? t1 : expm1f(t1);
        float t2 = acc[i][2] + b4[2]; v.z = (t2 > 0.f) ? t2 : expm1f(t2);
        float t3 = acc[i][3] + b4[3]; v.w = (t3 > 0.f) ? t3 : expm1f(t3);
        *(float4*)&C[(size_t)gm * H1DIM + tx * 4] = v;
    }
}

// ---------------- generic GEMM (layer 2): C[M,64] = A[M,K] @ B[K,64] ----------
__global__ void k_gemm(const float* __restrict__ A, const float* __restrict__ B,
                       float* __restrict__ C, int M, int N, int K) {
    __shared__ float As[16][129];
    __shared__ float Bs[16][68];

    int tid = threadIdx.x;
    int tx = tid & 15, ty = tid >> 4;
    int m0 = blockIdx.y * 128;
    int n0 = blockIdx.x * 64;

    float acc[8][4];
    #pragma unroll
    for (int i = 0; i < 8; i++)
        #pragma unroll
        for (int j = 0; j < 4; j++) acc[i][j] = 0.0f;

    for (int k0 = 0; k0 < K; k0 += 16) {
        #pragma unroll
        for (int q = 0; q < 2; q++) {
            int slot = tid + q * 256;
            int row = slot >> 2, kq = slot & 3;
            int gm = m0 + row;
            float4 v = make_float4(0.f, 0.f, 0.f, 0.f);
            if (gm < M) v = *(const float4*)&A[(size_t)gm * K + k0 + kq * 4];
            As[kq * 4 + 0][row] = v.x;
            As[kq * 4 + 1][row] = v.y;
            As[kq * 4 + 2][row] = v.z;
            As[kq * 4 + 3][row] = v.w;
        }
        {
            int kk = tid >> 4, col4 = (tid & 15) * 4;
            float4 v = *(const float4*)&B[(size_t)(k0 + kk) * N + n0 + col4];
            Bs[kk][col4 + 0] = v.x; Bs[kk][col4 + 1] = v.y;
            Bs[kk][col4 + 2] = v.z; Bs[kk][col4 + 3] = v.w;
        }
        __syncthreads();

        #pragma unroll
        for (int kk = 0; kk < 16; kk++) {
            float a[8], b[4];
            #pragma unroll
            for (int i = 0; i < 8; i++) a[i] = As[kk][ty * 8 + i];
            #pragma unroll
            for (int j = 0; j < 4; j++) b[j] = Bs[kk][tx * 4 + j];
            #pragma unroll
            for (int i = 0; i < 8; i++)
                #pragma unroll
                for (int j = 0; j < 4; j++) acc[i][j] = fmaf(a[i], b[j], acc[i][j]);
        }
        __syncthreads();
    }

    #pragma unroll
    for (int i = 0; i < 8; i++) {
        int gm = m0 + ty * 8 + i;
        if (gm >= M) continue;
        float4 v = make_float4(acc[i][0], acc[i][1], acc[i][2], acc[i][3]);
        *(float4*)&C[(size_t)gm * N + n0 + tx * 4] = v;
    }
}

// ---------------- layer-2 attention logits (warp per node) --------------------
__global__ void k_att2(const float* __restrict__ h2,
                       const float* __restrict__ att_src, const float* __restrict__ att_dst,
                       float* __restrict__ as2, float* __restrict__ ad2, int n) {
    int node = blockIdx.x * (blockDim.x / 32) + (threadIdx.x >> 5);
    int lane = threadIdx.x & 31;
    if (node >= n) return;
    const float* hp = &h2[(size_t)node * OUTC];
    float v0 = hp[lane], v1 = hp[lane + 32];
    float s = v0 * att_src[lane] + v1 * att_src[lane + 32];
    float d = v0 * att_dst[lane] + v1 * att_dst[lane + 32];
    #pragma unroll
    for (int o = 16; o > 0; o >>= 1) {
        s += __shfl_down_sync(0xffffffff, s, o);
        d += __shfl_down_sync(0xffffffff, d, o);
    }
    if (lane == 0) { as2[node] = s; ad2[node] = d; }
}

// ---------------- fused GAT layer 2 (warp per dst) ----------------------------
__global__ void k_gat2(const int* __restrict__ elist, const int* __restrict__ off,
                       const float* __restrict__ as2, const float* __restrict__ ad2,
                       const float* __restrict__ h2, const float* __restrict__ b2,
                       float* __restrict__ out, int n) {
    int dst = blockIdx.x * (blockDim.x / 32) + (threadIdx.x >> 5);
    int lane = threadIdx.x & 31;
    if (dst >= n) return;
    int beg = off[dst], end = off[dst + 1];
    float ad = ad2[dst];

    float m = -INFINITY, s = 0.f;
    for (int i = beg + lane; i < end; i += 32) {
        int src = elist[i];
        float e = as2[src] + ad;
        e = (e > 0.f) ? e : NEG_SLOPE * e;
        float nm = fmaxf(m, e);
        s = s * __expf(m - nm) + __expf(e - nm);
        m = nm;
    }
    #pragma unroll
    for (int o = 16; o > 0; o >>= 1) {
        float m2 = __shfl_xor_sync(0xffffffff, m, o);
        float s2 = __shfl_xor_sync(0xffffffff, s, o);
        float nm = fmaxf(m, m2);
        float w1 = (m  == -INFINITY) ? 0.f : __expf(m - nm);
        float w2 = (m2 == -INFINITY) ? 0.f : __expf(m2 - nm);
        s = s * w1 + s2 * w2;
        m = nm;
    }
    float invs = 1.0f / (s + EPSF);

    float acc0 = 0.f, acc1 = 0.f;
    for (int i = beg; i < end; i++) {
        int src = elist[i];
        float e = as2[src] + ad;
        e = (e > 0.f) ? e : NEG_SLOPE * e;
        float a = __expf(e - m) * invs;
        const float* hp = &h2[(size_t)src * OUTC];
        acc0 = fmaf(hp[lane],      a, acc0);
        acc1 = fmaf(hp[lane + 32], a, acc1);
    }
    float* op = &out[(size_t)dst * OUTC];
    op[lane]      = acc0 + b2[lane];
    op[lane + 32] = acc1 + b2[lane + 32];
}

// ---------------- launcher ----------------
extern "C" void kernel_launch(void* const* d_in, const int* in_sizes, int n_in,
                              void* d_out, int out_size) {
    float *p_aggx, *p_out1, *p_h2, *p_ws1, *p_as2, *p_ad2;
    float4 *p_s1, *p_d1;
    int *p_deg, *p_cur, *p_off, *p_elist;
    cudaGetSymbolAddress((void**)&p_aggx,  g_aggx);
    cudaGetSymbolAddress((void**)&p_out1,  g_out1);
    cudaGetSymbolAddress((void**)&p_h2,    g_h2);
    cudaGetSymbolAddress((void**)&p_ws1,   g_ws1);
    cudaGetSymbolAddress((void**)&p_s1,    g_s1);
    cudaGetSymbolAddress((void**)&p_d1,    g_d1);
    cudaGetSymbolAddress((void**)&p_as2,   g_as2);
    cudaGetSymbolAddress((void**)&p_ad2,   g_ad2);
    cudaGetSymbolAddress((void**)&p_deg,   g_deg);
    cudaGetSymbolAddress((void**)&p_cur,   g_cursor);
    cudaGetSymbolAddress((void**)&p_off,   g_off);
    cudaGetSymbolAddress((void**)&p_elist, g_elist);

    const float* x = nullptr; const int* ei = nullptr;
    const float* W1 = nullptr; const float* W2 = nullptr;
    const float* s192[3] = {nullptr, nullptr, nullptr}; int n192 = 0;
    const float* s64 [3] = {nullptr, nullptr, nullptr}; int n64  = 0;
    for (int i = 0; i < n_in; i++) {
        int sz = in_sizes[i];
        if      (sz == NN * INC)        x  = (const float*)d_in[i];
        else if (sz == 2 * EE)          ei = (const int*)  d_in[i];
        else if (sz == INC * H1DIM)     W1 = (const float*)d_in[i];
        else if (sz == H1DIM * OUTC)    W2 = (const float*)d_in[i];
        else if (sz == H1DIM && n192 < 3) s192[n192++] = (const float*)d_in[i];
        else if (sz == OUTC  && n64  < 3) s64 [n64++]  = (const float*)d_in[i];
    }
    const float* att_src1 = s192[0]; const float* att_dst1 = s192[1]; const float* b1 = s192[2];
    const float* att_src2 = s64[0];  const float* att_dst2 = s64[1];  const float* b2 = s64[2];

    float* out = (float*)d_out;
    int n  = NN;
    int e  = EE;
    int et = e + n;

    // CSR build
    k_init  <<<(n + 255) / 256, 256>>>(p_deg, p_cur, n);
    k_hist  <<<(et + 255) / 256, 256>>>(ei, p_deg, e, et);
    k_scan  <<<1, 1024>>>(p_deg, p_off, n);
    k_bucket<<<(et + 255) / 256, 256>>>(ei, p_off, p_cur, p_elist, e, et);

    // layer 1 (aggregate-then-transform)
    k_wvec  <<<3, 256>>>(W1, att_src1, att_dst1, p_ws1);
    k_logits<<<(n + 7) / 8, 256>>>(x, p_ws1, p_s1, p_d1, n);
    k_gat1x <<<(n + 7) / 8, 256>>>(p_elist, p_off, p_s1, p_d1, x, p_aggx, n);
    {
        dim3 grid(1, (n + 127) / 128, HEADS);
        k_gemm_l1<<<grid, 256>>>(p_aggx, W1, b1, p_out1, n);
    }

    // layer 2 (transform-then-aggregate)
    {
        dim3 grid(1, (n + 127) / 128);
        k_gemm<<<grid, 256>>>(p_out1, W2, p_h2, n, OUTC, H1DIM);
    }
    k_att2<<<(n + 3) / 4, 128>>>(p_h2, att_src2, att_dst2, p_as2, p_ad2, n);
    k_gat2<<<(n + 7) / 8, 256>>>(p_elist, p_off, p_as2, p_ad2, p_h2, b2, out, n);
}

// round 7
// speedup vs baseline: 1.1013x; 1.1013x over previous
#include <cuda_runtime.h>
#include <math.h>

#define NN     50000
#define EE     800000
#define ETMAX  (EE + NN)
#define INC    128
#define HEADS  3
#define HID    64
#define H1DIM  (HEADS * HID) // 192
#define OUTC   64

#define NEG_SLOPE 0.2f
#define EPSF 1e-16f

#define LRELU(t) (((t) > 0.f) ? (t) : NEG_SLOPE * (t))

// ---------------- scratch (static device globals; no allocations) -------------
__device__ float  g_h1  [(size_t)NN * H1DIM];   // x @ W1
__device__ float  g_out1[(size_t)NN * H1DIM];   // layer1 output (post ELU)
__device__ float  g_h2  [(size_t)NN * OUTC];    // out1 @ W2
__device__ float  g_ws1 [2 * HEADS * INC];      // folded att vectors
__device__ float4 g_s1  [NN];                   // packed (as0,as1,as2,_)
__device__ float4 g_d1  [NN];                   // packed (ad0,ad1,ad2,_)
__device__ float  g_as2 [NN];
__device__ float  g_ad2 [NN];
__device__ int    g_deg   [NN];
__device__ int    g_cursor[NN];
__device__ int    g_off   [NN + 1];
__device__ int    g_elist [ETMAX];

// ---------------- CSR build ---------------------------------------------------
__global__ void k_init(int* __restrict__ deg, int* __restrict__ cur, int n) {
    int i = blockIdx.x * blockDim.x + threadIdx.x;
    if (i < n) { deg[i] = 0; cur[i] = 0; }
}

__global__ void k_hist(const int* __restrict__ ei, int* __restrict__ deg,
                       int e_real, int et) {
    int i = blockIdx.x * blockDim.x + threadIdx.x;
    if (i >= et) return;
    int dst = (i < e_real) ? ei[e_real + i] : (i - e_real);
    atomicAdd(&deg[dst], 1);
}

__global__ void k_scan(const int* __restrict__ deg, int* __restrict__ off, int n) {
    __shared__ int part[1024];
    int t = threadIdx.x;
    int chunk = (n + 1023) / 1024;
    int b = t * chunk;
    int s = 0;
    for (int j = 0; j < chunk; j++) { int idx = b + j; if (idx < n) s += deg[idx]; }
    part[t] = s;
    __syncthreads();
    for (int d = 1; d < 1024; d <<= 1) {
        int v = (t >= d) ? part[t - d] : 0;
        __syncthreads();
        part[t] += v;
        __syncthreads();
    }
    int run = (t == 0) ? 0 : part[t - 1];
    for (int j = 0; j < chunk; j++) {
        int idx = b + j;
        if (idx < n) { off[idx] = run; run += deg[idx]; }
    }
    if (t == 1023) off[n] = part[1023];
}

__global__ void k_bucket(const int* __restrict__ ei, const int* __restrict__ off,
                         int* __restrict__ cur, int* __restrict__ elist,
                         int e_real, int et) {
    int i = blockIdx.x * blockDim.x + threadIdx.x;
    if (i >= et) return;
    int src, dst;
    if (i < e_real) { src = ei[i]; dst = ei[e_real + i]; }
    else            { src = i - e_real; dst = src; }
    int pos = atomicAdd(&cur[dst], 1);
    elist[off[dst] + pos] = src;
}

// ---------------- fold att vectors through W1 ---------------------------------
__global__ void k_wvec(const float* __restrict__ W1,
                       const float* __restrict__ att_s, const float* __restrict__ att_d,
                       float* __restrict__ ws) {
    int i = blockIdx.x * blockDim.x + threadIdx.x;   // 0..767
    if (i >= 2 * HEADS * INC) return;
    int sd = i / (HEADS * INC);
    int h  = (i / INC) % HEADS;
    int k  = i % INC;
    const float* att = sd ? att_d : att_s;
    float sum = 0.f;
    const float* wrow = &W1[(size_t)k * H1DIM + h * HID];
    const float* arow = &att[h * HID];
    #pragma unroll 8
    for (int c = 0; c < HID; c++) sum += wrow[c] * arow[c];
    ws[i] = sum;
}

// ---------------- per-node logits via GEMV on x (warp per node) ---------------
__global__ void k_logits(const float* __restrict__ x, const float* __restrict__ ws,
                         float4* __restrict__ s1, float4* __restrict__ d1, int n) {
    __shared__ float w[2 * HEADS * INC];
    for (int i = threadIdx.x; i < 2 * HEADS * INC; i += blockDim.x) w[i] = ws[i];
    __syncthreads();
    int node = blockIdx.x * (blockDim.x / 32) + (threadIdx.x >> 5);
    int lane = threadIdx.x & 31;
    if (node >= n) return;
    float4 xv = ((const float4*)(x + (size_t)node * INC))[lane];
    float r[6];
    #pragma unroll
    for (int j = 0; j < 6; j++) {
        const float* wv = &w[j * INC + lane * 4];
        r[j] = xv.x * wv[0] + xv.y * wv[1] + xv.z * wv[2] + xv.w * wv[3];
    }
    #pragma unroll
    for (int o = 16; o > 0; o >>= 1)
        #pragma unroll
        for (int j = 0; j < 6; j++) r[j] += __shfl_down_sync(0xffffffff, r[j], o);
    if (lane == 0) {
        s1[node] = make_float4(r[0], r[1], r[2], 0.f);
        d1[node] = make_float4(r[3], r[4], r[5], 0.f);
    }
}

// ---------------- GEMM: C[M,N] = A[M,K] @ B[K,N] ------------------------------
__global__ void k_gemm(const float* __restrict__ A, const float* __restrict__ B,
                       float* __restrict__ C, int M, int N, int K) {
    __shared__ float As[16][129];
    __shared__ float Bs[16][68];

    int tid = threadIdx.x;
    int tx = tid & 15, ty = tid >> 4;
    int m0 = blockIdx.y * 128;
    int n0 = blockIdx.x * 64;

    float acc[8][4];
    #pragma unroll
    for (int i = 0; i < 8; i++)
        #pragma unroll
        for (int j = 0; j < 4; j++) acc[i][j] = 0.0f;

    for (int k0 = 0; k0 < K; k0 += 16) {
        #pragma unroll
        for (int q = 0; q < 2; q++) {
            int slot = tid + q * 256;
            int row = slot >> 2, kq = slot & 3;
            int gm = m0 + row;
            float4 v = make_float4(0.f, 0.f, 0.f, 0.f);
            if (gm < M) v = *(const float4*)&A[(size_t)gm * K + k0 + kq * 4];
            As[kq * 4 + 0][row] = v.x;
            As[kq * 4 + 1][row] = v.y;
            As[kq * 4 + 2][row] = v.z;
            As[kq * 4 + 3][row] = v.w;
        }
        {
            int kk = tid >> 4, col4 = (tid & 15) * 4;
            float4 v = *(const float4*)&B[(size_t)(k0 + kk) * N + n0 + col4];
            Bs[kk][col4 + 0] = v.x; Bs[kk][col4 + 1] = v.y;
            Bs[kk][col4 + 2] = v.z; Bs[kk][col4 + 3] = v.w;
        }
        __syncthreads();

        #pragma unroll
        for (int kk = 0; kk < 16; kk++) {
            float a[8], b[4];
            #pragma unroll
            for (int i = 0; i < 8; i++) a[i] = As[kk][ty * 8 + i];
            #pragma unroll
            for (int j = 0; j < 4; j++) b[j] = Bs[kk][tx * 4 + j];
            #pragma unroll
            for (int i = 0; i < 8; i++)
                #pragma unroll
                for (int j = 0; j < 4; j++) acc[i][j] = fmaf(a[i], b[j], acc[i][j]);
        }
        __syncthreads();
    }

    #pragma unroll
    for (int i = 0; i < 8; i++) {
        int gm = m0 + ty * 8 + i;
        if (gm >= M) continue;
        float4 v = make_float4(acc[i][0], acc[i][1], acc[i][2], acc[i][3]);
        *(float4*)&C[(size_t)gm * N + n0 + tx * 4] = v;
    }
}

// ---------------- fused GAT layer 1: single-pass online softmax ---------------
// warp per dst. Lane layout: float4 -> channels 4*lane (head0 lanes 0-15,
// head1 lanes 16-31); float2 -> channels 128+2*lane (head2).
__global__ void k_gat1(const int* __restrict__ elist, const int* __restrict__ off,
                       const float4* __restrict__ sp1, const float4* __restrict__ dp1,
                       const float* __restrict__ h1, const float* __restrict__ b1,
                       float* __restrict__ out1, int n) {
    int dst = blockIdx.x * (blockDim.x >> 5) + (threadIdx.x >> 5);
    int lane = threadIdx.x & 31;
    if (dst >= n) return;
    int beg = off[dst], end = off[dst + 1];
    float4 ad = dp1[dst];
    bool is_h0 = (lane < 16);

    float mA = -INFINITY, mB = -INFINITY, sA = 0.f, sB = 0.f;
    float4 acc4 = make_float4(0.f, 0.f, 0.f, 0.f);
    float2 acc2 = make_float2(0.f, 0.f);

    int i = beg;
    for (; i + 4 <= end; i += 4) {
        int e0 = elist[i], e1 = elist[i + 1], e2 = elist[i + 2], e3 = elist[i + 3];
        float4 q0 = sp1[e0], q1 = sp1[e1], q2 = sp1[e2], q3 = sp1[e3];
        const float* r0 = h1 + (size_t)e0 * H1DIM;
        const float* r1 = h1 + (size_t)e1 * H1DIM;
        const float* r2 = h1 + (size_t)e2 * H1DIM;
        const float* r3 = h1 + (size_t)e3 * H1DIM;
        float4 x0 = ((const float4*)r0)[lane];
        float4 x1 = ((const float4*)r1)[lane];
        float4 x2 = ((const float4*)r2)[lane];
        float4 x3 = ((const float4*)r3)[lane];
        float2 y0 = *(const float2*)(r0 + 128 + 2 * lane);
        float2 y1 = *(const float2*)(r1 + 128 + 2 * lane);
        float2 y2 = *(const float2*)(r2 + 128 + 2 * lane);
        float2 y3 = *(const float2*)(r3 + 128 + 2 * lane);

        float vA0 = LRELU(is_h0 ? (q0.x + ad.x) : (q0.y + ad.y));
        float vA1 = LRELU(is_h0 ? (q1.x + ad.x) : (q1.y + ad.y));
        float vA2 = LRELU(is_h0 ? (q2.x + ad.x) : (q2.y + ad.y));
        float vA3 = LRELU(is_h0 ? (q3.x + ad.x) : (q3.y + ad.y));
        float vB0 = LRELU(q0.z + ad.z);
        float vB1 = LRELU(q1.z + ad.z);
        float vB2 = LRELU(q2.z + ad.z);
        float vB3 = LRELU(q3.z + ad.z);

        float bmA = fmaxf(fmaxf(vA0, vA1), fmaxf(vA2, vA3));
        if (bmA > mA) {
            float sc = __expf(mA - bmA);
            sA *= sc; acc4.x *= sc; acc4.y *= sc; acc4.z *= sc; acc4.w *= sc;
            mA = bmA;
        }
        float bmB = fmaxf(fmaxf(vB0, vB1), fmaxf(vB2, vB3));
        if (bmB > mB) {
            float sc = __expf(mB - bmB);
            sB *= sc; acc2.x *= sc; acc2.y *= sc;
            mB = bmB;
        }
        float pA0 = __expf(vA0 - mA), pA1 = __expf(vA1 - mA);
        float pA2 = __expf(vA2 - mA), pA3 = __expf(vA3 - mA);
        float pB0 = __expf(vB0 - mB), pB1 = __expf(vB1 - mB);
        float pB2 = __expf(vB2 - mB), pB3 = __expf(vB3 - mB);
        sA += (pA0 + pA1) + (pA2 + pA3);
        sB += (pB0 + pB1) + (pB2 + pB3);
        acc4.x = fmaf(x0.x, pA0, acc4.x); acc4.y = fmaf(x0.y, pA0, acc4.y);
        acc4.z = fmaf(x0.z, pA0, acc4.z); acc4.w = fmaf(x0.w, pA0, acc4.w);
        acc4.x = fmaf(x1.x, pA1, acc4.x); acc4.y = fmaf(x1.y, pA1, acc4.y);
        acc4.z = fmaf(x1.z, pA1, acc4.z); acc4.w = fmaf(x1.w, pA1, acc4.w);
        acc4.x = fmaf(x2.x, pA2, acc4.x); acc4.y = fmaf(x2.y, pA2, acc4.y);
        acc4.z = fmaf(x2.z, pA2, acc4.z); acc4.w = fmaf(x2.w, pA2, acc4.w);
        acc4.x = fmaf(x3.x, pA3, acc4.x); acc4.y = fmaf(x3.y, pA3, acc4.y);
        acc4.z = fmaf(x3.z, pA3, acc4.z); acc4.w = fmaf(x3.w, pA3, acc4.w);
        acc2.x = fmaf(y0.x, pB0, acc2.x); acc2.y = fmaf(y0.y, pB0, acc2.y);
        acc2.x = fmaf(y1.x, pB1, acc2.x); acc2.y = fmaf(y1.y, pB1, acc2.y);
        acc2.x = fmaf(y2.x, pB2, acc2.x); acc2.y = fmaf(y2.y, pB2, acc2.y);
        acc2.x = fmaf(y3.x, pB3, acc2.x); acc2.y = fmaf(y3.y, pB3, acc2.y);
    }
    for (; i < end; i++) {
        int e0 = elist[i];
        float4 q0 = sp1[e0];
        const float* r0 = h1 + (size_t)e0 * H1DIM;
        float4 x0 = ((const float4*)r0)[lane];
        float2 y0 = *(const float2*)(r0 + 128 + 2 * lane);
        float vA0 = LRELU(is_h0 ? (q0.x + ad.x) : (q0.y + ad.y));
        float vB0 = LRELU(q0.z + ad.z);
        if (vA0 > mA) {
            float sc = __expf(mA - vA0);
            sA *= sc; acc4.x *= sc; acc4.y *= sc; acc4.z *= sc; acc4.w *= sc;
            mA = vA0;
        }
        if (vB0 > mB) {
            float sc = __expf(mB - vB0);
            sB *= sc; acc2.x *= sc; acc2.y *= sc;
            mB = vB0;
        }
        float pA0 = __expf(vA0 - mA);
        float pB0 = __expf(vB0 - mB);
        sA += pA0; sB += pB0;
        acc4.x = fmaf(x0.x, pA0, acc4.x); acc4.y = fmaf(x0.y, pA0, acc4.y);
        acc4.z = fmaf(x0.z, pA0, acc4.z); acc4.w = fmaf(x0.w, pA0, acc4.w);
        acc2.x = fmaf(y0.x, pB0, acc2.x); acc2.y = fmaf(y0.y, pB0, acc2.y);
    }

    float invA = 1.0f / (sA + EPSF);
    float invB = 1.0f / (sB + EPSF);
    float* op = out1 + (size_t)dst * H1DIM;
    float4 bb4 = ((const float4*)b1)[lane];
    float2 bb2 = *(const float2*)(b1 + 128 + 2 * lane);
    float4 o4; float2 o2; float t;
    t = fmaf(acc4.x, invA, bb4.x); o4.x = (t > 0.f) ? t : expm1f(t);
    t = fmaf(acc4.y, invA, bb4.y); o4.y = (t > 0.f) ? t : expm1f(t);
    t = fmaf(acc4.z, invA, bb4.z); o4.z = (t > 0.f) ? t : expm1f(t);
    t = fmaf(acc4.w, invA, bb4.w); o4.w = (t > 0.f) ? t : expm1f(t);
    t = fmaf(acc2.x, invB, bb2.x); o2.x = (t > 0.f) ? t : expm1f(t);
    t = fmaf(acc2.y, invB, bb2.y); o2.y = (t > 0.f) ? t : expm1f(t);
    ((float4*)op)[lane] = o4;
    *(float2*)(op + 128 + 2 * lane) = o2;
}

// ---------------- layer-2 attention logits (warp per node) --------------------
__global__ void k_att2(const float* __restrict__ h2,
                       const float* __restrict__ att_src, const float* __restrict__ att_dst,
                       float* __restrict__ as2, float* __restrict__ ad2, int n) {
    int node = blockIdx.x * (blockDim.x / 32) + (threadIdx.x >> 5);
    int lane = threadIdx.x & 31;
    if (node >= n) return;
    const float* hp = &h2[(size_t)node * OUTC];
    float v0 = hp[lane], v1 = hp[lane + 32];
    float s = v0 * att_src[lane] + v1 * att_src[lane + 32];
    float d = v0 * att_dst[lane] + v1 * att_dst[lane + 32];
    #pragma unroll
    for (int o = 16; o > 0; o >>= 1) {
        s += __shfl_down_sync(0xffffffff, s, o);
        d += __shfl_down_sync(0xffffffff, d, o);
    }
    if (lane == 0) { as2[node] = s; ad2[node] = d; }
}

// ---------------- fused GAT layer 2: single-pass online softmax ---------------
// warp per dst; lane covers channels 2*lane, 2*lane+1.
__global__ void k_gat2(const int* __restrict__ elist, const int* __restrict__ off,
                       const float* __restrict__ as2, const float* __restrict__ ad2,
                       const float* __restrict__ h2, const float* __restrict__ b2,
                       float* __restrict__ out, int n) {
    int dst = blockIdx.x * (blockDim.x >> 5) + (threadIdx.x >> 5);
    int lane = threadIdx.x & 31;
    if (dst >= n) return;
    int beg = off[dst], end = off[dst + 1];
    float ad = ad2[dst];

    float m = -INFINITY, s = 0.f;
    float2 acc = make_float2(0.f, 0.f);

    int i = beg;
    for (; i + 4 <= end; i += 4) {
        int e0 = elist[i], e1 = elist[i + 1], e2 = elist[i + 2], e3 = elist[i + 3];
        float a0 = as2[e0], a1 = as2[e1], a2 = as2[e2], a3 = as2[e3];
        float2 y0 = *(const float2*)(h2 + (size_t)e0 * OUTC + 2 * lane);
        float2 y1 = *(const float2*)(h2 + (size_t)e1 * OUTC + 2 * lane);
        float2 y2 = *(const float2*)(h2 + (size_t)e2 * OUTC + 2 * lane);
        float2 y3 = *(const float2*)(h2 + (size_t)e3 * OUTC + 2 * lane);
        float v0 = LRELU(a0 + ad), v1 = LRELU(a1 + ad);
        float v2 = LRELU(a2 + ad), v3 = LRELU(a3 + ad);
        float bm = fmaxf(fmaxf(v0, v1), fmaxf(v2, v3));
        if (bm > m) {
            float sc = __expf(m - bm);
            s *= sc; acc.x *= sc; acc.y *= sc;
            m = bm;
        }
        float p0 = __expf(v0 - m), p1 = __expf(v1 - m);
        float p2 = __expf(v2 - m), p3 = __expf(v3 - m);
        s += (p0 + p1) + (p2 + p3);
        acc.x = fmaf(y0.x, p0, acc.x); acc.y = fmaf(y0.y, p0, acc.y);
        acc.x = fmaf(y1.x, p1, acc.x); acc.y = fmaf(y1.y, p1, acc.y);
        acc.x = fmaf(y2.x, p2, acc.x); acc.y = fmaf(y2.y, p2, acc.y);
        acc.x = fmaf(y3.x, p3, acc.x); acc.y = fmaf(y3.y, p3, acc.y);
    }
    for (; i < end; i++) {
        int e0 = elist[i];
        float a0 = as2[e0];
        float2 y0 = *(const float2*)(h2 + (size_t)e0 * OUTC + 2 * lane);
        float v0 = LRELU(a0 + ad);
        if (v0 > m) {
            float sc = __expf(m - v0);
            s *= sc; acc.x *= sc; acc.y *= sc;
            m = v0;
        }
        float p0 = __expf(v0 - m);
        s += p0;
        acc.x = fmaf(y0.x, p0, acc.x); acc.y = fmaf(y0.y, p0, acc.y);
    }

    float inv = 1.0f / (s + EPSF);
    float2 bb = *(const float2*)(b2 + 2 * lane);
    float2 o;
    o.x = fmaf(acc.x, inv, bb.x);
    o.y = fmaf(acc.y, inv, bb.y);
    *(float2*)(out + (size_t)dst * OUTC + 2 * lane) = o;
}

// ---------------- launcher ----------------
extern "C" void kernel_launch(void* const* d_in, const int* in_sizes, int n_in,
                              void* d_out, int out_size) {
    float *p_h1, *p_out1, *p_h2, *p_ws1, *p_as2, *p_ad2;
    float4 *p_s1, *p_d1;
    int *p_deg, *p_cur, *p_off, *p_elist;
    cudaGetSymbolAddress((void**)&p_h1,    g_h1);
    cudaGetSymbolAddress((void**)&p_out1,  g_out1);
    cudaGetSymbolAddress((void**)&p_h2,    g_h2);
    cudaGetSymbolAddress((void**)&p_ws1,   g_ws1);
    cudaGetSymbolAddress((void**)&p_s1,    g_s1);
    cudaGetSymbolAddress((void**)&p_d1,    g_d1);
    cudaGetSymbolAddress((void**)&p_as2,   g_as2);
    cudaGetSymbolAddress((void**)&p_ad2,   g_ad2);
    cudaGetSymbolAddress((void**)&p_deg,   g_deg);
    cudaGetSymbolAddress((void**)&p_cur,   g_cursor);
    cudaGetSymbolAddress((void**)&p_off,   g_off);
    cudaGetSymbolAddress((void**)&p_elist, g_elist);

    const float* x = nullptr; const int* ei = nullptr;
    const float* W1 = nullptr; const float* W2 = nullptr;
    const float* s192[3] = {nullptr, nullptr, nullptr}; int n192 = 0;
    const float* s64 [3] = {nullptr, nullptr, nullptr}; int n64  = 0;
    for (int i = 0; i < n_in; i++) {
        int sz = in_sizes[i];
        if      (sz == NN * INC)        x  = (const float*)d_in[i];
        else if (sz == 2 * EE)          ei = (const int*)  d_in[i];
        else if (sz == INC * H1DIM)     W1 = (const float*)d_in[i];
        else if (sz == H1DIM * OUTC)    W2 = (const float*)d_in[i];
        else if (sz == H1DIM && n192 < 3) s192[n192++] = (const float*)d_in[i];
        else if (sz == OUTC  && n64  < 3) s64 [n64++]  = (const float*)d_in[i];
    }
    const float* att_src1 = s192[0]; const float* att_dst1 = s192[1]; const float* b1 = s192[2];
    const float* att_src2 = s64[0];  const float* att_dst2 = s64[1];  const float* b2 = s64[2];

    float* out = (float*)d_out;
    int n  = NN;
    int e  = EE;
    int et = e + n;

    // CSR build
    k_init  <<<(n + 255) / 256, 256>>>(p_deg, p_cur, n);
    k_hist  <<<(et + 255) / 256, 256>>>(ei, p_deg, e, et);
    k_scan  <<<1, 1024>>>(p_deg, p_off, n);
    k_bucket<<<(et + 255) / 256, 256>>>(ei, p_off, p_cur, p_elist, e, et);

    // layer 1
    k_wvec  <<<3, 256>>>(W1, att_src1, att_dst1, p_ws1);
    k_logits<<<(n + 7) / 8, 256>>>(x, p_ws1, p_s1, p_d1, n);
    {
        dim3 grid(H1DIM / 64, (n + 127) / 128);
        k_gemm<<<grid, 256>>>(x, W1, p_h1, n, H1DIM, INC);
    }
    k_gat1<<<(n + 15) / 16, 512>>>(p_elist, p_off, p_s1, p_d1, p_h1, b1, p_out1, n);

    // layer 2
    {
        dim3 grid(1, (n + 127) / 128);
        k_gemm<<<grid, 256>>>(p_out1, W2, p_h2, n, OUTC, H1DIM);
    }
    k_att2<<<(n + 3) / 4, 128>>>(p_h2, att_src2, att_dst2, p_as2, p_ad2, n);
    k_gat2<<<(n + 15) / 16, 512>>>(p_elist, p_off, p_as2, p_ad2, p_h2, b2, out, n);
}

// round 12
// speedup vs baseline: 1.3721x; 1.2459x over previous
#include <cuda_runtime.h>
#include <math.h>

#define NN     50000
#define EE     800000
#define ETMAX  (EE + NN)
#define INC    128
#define HEADS  3
#define HID    64
#define H1DIM  (HEADS * HID) // 192
#define OUTC   64

#define NEG_SLOPE 0.2f
#define EPSF 1e-16f

#define LRELU(t) (((t) > 0.f) ? (t) : NEG_SLOPE * (t))

// ---------------- scratch (static device globals; no allocations) -------------
__device__ float  g_h1  [(size_t)NN * H1DIM];   // x @ W1
__device__ float  g_out1[(size_t)NN * H1DIM];   // layer1 output (post ELU)
__device__ float  g_h2  [(size_t)NN * OUTC];    // out1 @ W2
__device__ float  g_ws1 [2 * HEADS * INC];      // folded att vectors
__device__ float4 g_s1  [NN];                   // packed (as0,as1,as2,_)
__device__ float4 g_d1  [NN];                   // packed (ad0,ad1,ad2,_)
__device__ float  g_as2 [NN];
__device__ float  g_ad2 [NN];
__device__ int    g_deg   [NN];
__device__ int    g_cursor[NN];
__device__ int    g_off   [NN + 1];
__device__ int    g_elist [ETMAX];

// ---------------- CSR build ---------------------------------------------------
__global__ void k_hist(const int* __restrict__ ei, int* __restrict__ deg,
                       int e_real, int et) {
    int i = blockIdx.x * blockDim.x + threadIdx.x;
    if (i >= et) return;
    int dst = (i < e_real) ? ei[e_real + i] : (i - e_real);
    atomicAdd(&deg[dst], 1);
}

// single-block scan; also zeroes cursor
__global__ void k_scan(const int* __restrict__ deg, int* __restrict__ off,
                       int* __restrict__ cur, int n) {
    __shared__ int part[1024];
    int t = threadIdx.x;
    int chunk = (n + 1023) / 1024;
    int b = t * chunk;
    int s = 0;
    for (int j = 0; j < chunk; j++) { int idx = b + j; if (idx < n) s += deg[idx]; }
    part[t] = s;
    __syncthreads();
    for (int d = 1; d < 1024; d <<= 1) {
        int v = (t >= d) ? part[t - d] : 0;
        __syncthreads();
        part[t] += v;
        __syncthreads();
    }
    int run = (t == 0) ? 0 : part[t - 1];
    for (int j = 0; j < chunk; j++) {
        int idx = b + j;
        if (idx < n) { off[idx] = run; run += deg[idx]; cur[idx] = 0; }
    }
    if (t == 1023) off[n] = part[1023];
}

__global__ void k_bucket(const int* __restrict__ ei, const int* __restrict__ off,
                         int* __restrict__ cur, int* __restrict__ elist,
                         int e_real, int et) {
    int i = blockIdx.x * blockDim.x + threadIdx.x;
    if (i >= et) return;
    int src, dst;
    if (i < e_real) { src = ei[i]; dst = ei[e_real + i]; }
    else            { src = i - e_real; dst = src; }
    int pos = atomicAdd(&cur[dst], 1);
    elist[off[dst] + pos] = src;
}

// ---------------- fold att vectors through W1 ---------------------------------
__global__ void k_wvec(const float* __restrict__ W1,
                       const float* __restrict__ att_s, const float* __restrict__ att_d,
                       float* __restrict__ ws) {
    int i = blockIdx.x * blockDim.x + threadIdx.x;   // 0..767
    if (i >= 2 * HEADS * INC) return;
    int sd = i / (HEADS * INC);
    int h  = (i / INC) % HEADS;
    int k  = i % INC;
    const float* att = sd ? att_d : att_s;
    float sum = 0.f;
    const float* wrow = &W1[(size_t)k * H1DIM + h * HID];
    const float* arow = &att[h * HID];
    #pragma unroll 8
    for (int c = 0; c < HID; c++) sum += wrow[c] * arow[c];
    ws[i] = sum;
}

// ---------------- per-node logits via GEMV on x (warp per node) ---------------
__global__ void k_logits(const float* __restrict__ x, const float* __restrict__ ws,
                         float4* __restrict__ s1, float4* __restrict__ d1, int n) {
    __shared__ float w[2 * HEADS * INC];
    for (int i = threadIdx.x; i < 2 * HEADS * INC; i += blockDim.x) w[i] = ws[i];
    __syncthreads();
    int node = blockIdx.x * (blockDim.x / 32) + (threadIdx.x >> 5);
    int lane = threadIdx.x & 31;
    if (node >= n) return;
    float4 xv = ((const float4*)(x + (size_t)node * INC))[lane];
    float r[6];
    #pragma unroll
    for (int j = 0; j < 6; j++) {
        const float* wv = &w[j * INC + lane * 4];
        r[j] = xv.x * wv[0] + xv.y * wv[1] + xv.z * wv[2] + xv.w * wv[3];
    }
    #pragma unroll
    for (int o = 16; o > 0; o >>= 1)
        #pragma unroll
        for (int j = 0; j < 6; j++) r[j] += __shfl_down_sync(0xffffffff, r[j], o);
    if (lane == 0) {
        s1[node] = make_float4(r[0], r[1], r[2], 0.f);
        d1[node] = make_float4(r[3], r[4], r[5], 0.f);
    }
}

// ---------------- GEMM: C[M,N] = A[M,K] @ B[K,N] ------------------------------
__global__ void k_gemm(const float* __restrict__ A, const float* __restrict__ B,
                       float* __restrict__ C, int M, int N, int K) {
    __shared__ float As[16][129];
    __shared__ float Bs[16][68];

    int tid = threadIdx.x;
    int tx = tid & 15, ty = tid >> 4;
    int m0 = blockIdx.y * 128;
    int n0 = blockIdx.x * 64;

    float acc[8][4];
    #pragma unroll
    for (int i = 0; i < 8; i++)
        #pragma unroll
        for (int j = 0; j < 4; j++) acc[i][j] = 0.0f;

    for (int k0 = 0; k0 < K; k0 += 16) {
        #pragma unroll
        for (int q = 0; q < 2; q++) {
            int slot = tid + q * 256;
            int row = slot >> 2, kq = slot & 3;
            int gm = m0 + row;
            float4 v = make_float4(0.f, 0.f, 0.f, 0.f);
            if (gm < M) v = *(const float4*)&A[(size_t)gm * K + k0 + kq * 4];
            As[kq * 4 + 0][row] = v.x;
            As[kq * 4 + 1][row] = v.y;
            As[kq * 4 + 2][row] = v.z;
            As[kq * 4 + 3][row] = v.w;
        }
        {
            int kk = tid >> 4, col4 = (tid & 15) * 4;
            float4 v = *(const float4*)&B[(size_t)(k0 + kk) * N + n0 + col4];
            Bs[kk][col4 + 0] = v.x; Bs[kk][col4 + 1] = v.y;
            Bs[kk][col4 + 2] = v.z; Bs[kk][col4 + 3] = v.w;
        }
        __syncthreads();

        #pragma unroll
        for (int kk = 0; kk < 16; kk++) {
            float a[8], b[4];
            #pragma unroll
            for (int i = 0; i < 8; i++) a[i] = As[kk][ty * 8 + i];
            #pragma unroll
            for (int j = 0; j < 4; j++) b[j] = Bs[kk][tx * 4 + j];
            #pragma unroll
            for (int i = 0; i < 8; i++)
                #pragma unroll
                for (int j = 0; j < 4; j++) acc[i][j] = fmaf(a[i], b[j], acc[i][j]);
        }
        __syncthreads();
    }

    #pragma unroll
    for (int i = 0; i < 8; i++) {
        int gm = m0 + ty * 8 + i;
        if (gm >= M) continue;
        float4 v = make_float4(acc[i][0], acc[i][1], acc[i][2], acc[i][3]);
        *(float4*)&C[(size_t)gm * N + n0 + tx * 4] = v;
    }
}

// ---------------- GEMM2 (N=64, K=192) with fused att2 logits ------------------
__global__ void k_gemm2(const float* __restrict__ A, const float* __restrict__ B,
                        const float* __restrict__ att_s, const float* __restrict__ att_d,
                        float* __restrict__ C, float* __restrict__ as2,
                        float* __restrict__ ad2, int M) {
    __shared__ float As[16][129];
    __shared__ float Bs[16][68];

    int tid = threadIdx.x;
    int tx = tid & 15, ty = tid >> 4;
    int m0 = blockIdx.y * 128;

    float acc[8][4];
    #pragma unroll
    for (int i = 0; i < 8; i++)
        #pragma unroll
        for (int j = 0; j < 4; j++) acc[i][j] = 0.0f;

    for (int k0 = 0; k0 < H1DIM; k0 += 16) {
        #pragma unroll
        for (int q = 0; q < 2; q++) {
            int slot = tid + q * 256;
            int row = slot >> 2, kq = slot & 3;
            int gm = m0 + row;
            float4 v = make_float4(0.f, 0.f, 0.f, 0.f);
            if (gm < M) v = *(const float4*)&A[(size_t)gm * H1DIM + k0 + kq * 4];
            As[kq * 4 + 0][row] = v.x;
            As[kq * 4 + 1][row] = v.y;
            As[kq * 4 + 2][row] = v.z;
            As[kq * 4 + 3][row] = v.w;
        }
        {
            int kk = tid >> 4, col4 = (tid & 15) * 4;
            float4 v = *(const float4*)&B[(size_t)(k0 + kk) * OUTC + col4];
            Bs[kk][col4 + 0] = v.x; Bs[kk][col4 + 1] = v.y;
            Bs[kk][col4 + 2] = v.z; Bs[kk][col4 + 3] = v.w;
        }
        __syncthreads();

        #pragma unroll
        for (int kk = 0; kk < 16; kk++) {
            float a[8], b[4];
            #pragma unroll
            for (int i = 0; i < 8; i++) a[i] = As[kk][ty * 8 + i];
            #pragma unroll
            for (int j = 0; j < 4; j++) b[j] = Bs[kk][tx * 4 + j];
            #pragma unroll
            for (int i = 0; i < 8; i++)
                #pragma unroll
                for (int j = 0; j < 4; j++) acc[i][j] = fmaf(a[i], b[j], acc[i][j]);
        }
        __syncthreads();
    }

    float avs[4], avd[4];
    #pragma unroll
    for (int j = 0; j < 4; j++) {
        avs[j] = att_s[tx * 4 + j];
        avd[j] = att_d[tx * 4 + j];
    }

    #pragma unroll
    for (int i = 0; i < 8; i++) {
        int gm = m0 + ty * 8 + i;
        float ps = 0.f, pd = 0.f;
        #pragma unroll
        for (int j = 0; j < 4; j++) {
            ps = fmaf(acc[i][j], avs[j], ps);
            pd = fmaf(acc[i][j], avd[j], pd);
        }
        #pragma unroll
        for (int o = 8; o > 0; o >>= 1) {
            ps += __shfl_down_sync(0xffffffff, ps, o, 16);
            pd += __shfl_down_sync(0xffffffff, pd, o, 16);
        }
        if (gm < M) {
            float4 v = make_float4(acc[i][0], acc[i][1], acc[i][2], acc[i][3]);
            *(float4*)&C[(size_t)gm * OUTC + tx * 4] = v;
            if (tx == 0) { as2[gm] = ps; ad2[gm] = pd; }
        }
    }
}

// ---------------- fused GAT layer 1: single-pass online softmax ---------------
__global__ void k_gat1(const int* __restrict__ elist, const int* __restrict__ off,
                       const float4* __restrict__ sp1, const float4* __restrict__ dp1,
                       const float* __restrict__ h1, const float* __restrict__ b1,
                       float* __restrict__ out1, int n) {
    int dst = blockIdx.x * (blockDim.x >> 5) + (threadIdx.x >> 5);
    int lane = threadIdx.x & 31;
    if (dst >= n) return;
    int beg = off[dst], end = off[dst + 1];
    float4 ad = dp1[dst];
    bool is_h0 = (lane < 16);

    float mA = -INFINITY, mB = -INFINITY, sA = 0.f, sB = 0.f;
    float4 acc4 = make_float4(0.f, 0.f, 0.f, 0.f);
    float2 acc2 = make_float2(0.f, 0.f);

    int i = beg;
    for (; i + 4 <= end; i += 4) {
        int e0 = elist[i], e1 = elist[i + 1], e2 = elist[i + 2], e3 = elist[i + 3];
        float4 q0 = sp1[e0], q1 = sp1[e1], q2 = sp1[e2], q3 = sp1[e3];
        const float* r0 = h1 + (size_t)e0 * H1DIM;
        const float* r1 = h1 + (size_t)e1 * H1DIM;
        const float* r2 = h1 + (size_t)e2 * H1DIM;
        const float* r3 = h1 + (size_t)e3 * H1DIM;
        float4 x0 = ((const float4*)r0)[lane];
        float4 x1 = ((const float4*)r1)[lane];
        float4 x2 = ((const float4*)r2)[lane];
        float4 x3 = ((const float4*)r3)[lane];
        float2 y0 = *(const float2*)(r0 + 128 + 2 * lane);
        float2 y1 = *(const float2*)(r1 + 128 + 2 * lane);
        float2 y2 = *(const float2*)(r2 + 128 + 2 * lane);
        float2 y3 = *(const float2*)(r3 + 128 + 2 * lane);

        float vA0 = LRELU(is_h0 ? (q0.x + ad.x) : (q0.y + ad.y));
        float vA1 = LRELU(is_h0 ? (q1.x + ad.x) : (q1.y + ad.y));
        float vA2 = LRELU(is_h0 ? (q2.x + ad.x) : (q2.y + ad.y));
        float vA3 = LRELU(is_h0 ? (q3.x + ad.x) : (q3.y + ad.y));
        float vB0 = LRELU(q0.z + ad.z);
        float vB1 = LRELU(q1.z + ad.z);
        float vB2 = LRELU(q2.z + ad.z);
        float vB3 = LRELU(q3.z + ad.z);

        float bmA = fmaxf(fmaxf(vA0, vA1), fmaxf(vA2, vA3));
        if (bmA > mA) {
            float sc = __expf(mA - bmA);
            sA *= sc; acc4.x *= sc; acc4.y *= sc; acc4.z *= sc; acc4.w *= sc;
            mA = bmA;
        }
        float bmB = fmaxf(fmaxf(vB0, vB1), fmaxf(vB2, vB3));
        if (bmB > mB) {
            float sc = __expf(mB - bmB);
            sB *= sc; acc2.x *= sc; acc2.y *= sc;
            mB = bmB;
        }
        float pA0 = __expf(vA0 - mA), pA1 = __expf(vA1 - mA);
        float pA2 = __expf(vA2 - mA), pA3 = __expf(vA3 - mA);
        float pB0 = __expf(vB0 - mB), pB1 = __expf(vB1 - mB);
        float pB2 = __expf(vB2 - mB), pB3 = __expf(vB3 - mB);
        sA += (pA0 + pA1) + (pA2 + pA3);
        sB += (pB0 + pB1) + (pB2 + pB3);
        acc4.x = fmaf(x0.x, pA0, acc4.x); acc4.y = fmaf(x0.y, pA0, acc4.y);
        acc4.z = fmaf(x0.z, pA0, acc4.z); acc4.w = fmaf(x0.w, pA0, acc4.w);
        acc4.x = fmaf(x1.x, pA1, acc4.x); acc4.y = fmaf(x1.y, pA1, acc4.y);
        acc4.z = fmaf(x1.z, pA1, acc4.z); acc4.w = fmaf(x1.w, pA1, acc4.w);
        acc4.x = fmaf(x2.x, pA2, acc4.x); acc4.y = fmaf(x2.y, pA2, acc4.y);
        acc4.z = fmaf(x2.z, pA2, acc4.z); acc4.w = fmaf(x2.w, pA2, acc4.w);
        acc4.x = fmaf(x3.x, pA3, acc4.x); acc4.y = fmaf(x3.y, pA3, acc4.y);
        acc4.z = fmaf(x3.z, pA3, acc4.z); acc4.w = fmaf(x3.w, pA3, acc4.w);
        acc2.x = fmaf(y0.x, pB0, acc2.x); acc2.y = fmaf(y0.y, pB0, acc2.y);
        acc2.x = fmaf(y1.x, pB1, acc2.x); acc2.y = fmaf(y1.y, pB1, acc2.y);
        acc2.x = fmaf(y2.x, pB2, acc2.x); acc2.y = fmaf(y2.y, pB2, acc2.y);
        acc2.x = fmaf(y3.x, pB3, acc2.x); acc2.y = fmaf(y3.y, pB3, acc2.y);
    }
    for (; i < end; i++) {
        int e0 = elist[i];
        float4 q0 = sp1[e0];
        const float* r0 = h1 + (size_t)e0 * H1DIM;
        float4 x0 = ((const float4*)r0)[lane];
        float2 y0 = *(const float2*)(r0 + 128 + 2 * lane);
        float vA0 = LRELU(is_h0 ? (q0.x + ad.x) : (q0.y + ad.y));
        float vB0 = LRELU(q0.z + ad.z);
        if (vA0 > mA) {
            float sc = __expf(mA - vA0);
            sA *= sc; acc4.x *= sc; acc4.y *= sc; acc4.z *= sc; acc4.w *= sc;
            mA = vA0;
        }
        if (vB0 > mB) {
            float sc = __expf(mB - vB0);
            sB *= sc; acc2.x *= sc; acc2.y *= sc;
            mB = vB0;
        }
        float pA0 = __expf(vA0 - mA);
        float pB0 = __expf(vB0 - mB);
        sA += pA0; sB += pB0;
        acc4.x = fmaf(x0.x, pA0, acc4.x); acc4.y = fmaf(x0.y, pA0, acc4.y);
        acc4.z = fmaf(x0.z, pA0, acc4.z); acc4.w = fmaf(x0.w, pA0, acc4.w);
        acc2.x = fmaf(y0.x, pB0, acc2.x); acc2.y = fmaf(y0.y, pB0, acc2.y);
    }

    float invA = 1.0f / (sA + EPSF);
    float invB = 1.0f / (sB + EPSF);
    float* op = out1 + (size_t)dst * H1DIM;
    float4 bb4 = ((const float4*)b1)[lane];
    float2 bb2 = *(const float2*)(b1 + 128 + 2 * lane);
    float4 o4; float2 o2; float t;
    t = fmaf(acc4.x, invA, bb4.x); o4.x = (t > 0.f) ? t : expm1f(t);
    t = fmaf(acc4.y, invA, bb4.y); o4.y = (t > 0.f) ? t : expm1f(t);
    t = fmaf(acc4.z, invA, bb4.z); o4.z = (t > 0.f) ? t : expm1f(t);
    t = fmaf(acc4.w, invA, bb4.w); o4.w = (t > 0.f) ? t : expm1f(t);
    t = fmaf(acc2.x, invB, bb2.x); o2.x = (t > 0.f) ? t : expm1f(t);
    t = fmaf(acc2.y, invB, bb2.y); o2.y = (t > 0.f) ? t : expm1f(t);
    ((float4*)op)[lane] = o4;
    *(float2*)(op + 128 + 2 * lane) = o2;
}

// ---------------- fused GAT layer 2: single-pass online softmax ---------------
__global__ void k_gat2(const int* __restrict__ elist, const int* __restrict__ off,
                       const float* __restrict__ as2, const float* __restrict__ ad2,
                       const float* __restrict__ h2, const float* __restrict__ b2,
                       float* __restrict__ out, int n) {
    int dst = blockIdx.x * (blockDim.x >> 5) + (threadIdx.x >> 5);
    int lane = threadIdx.x & 31;
    if (dst >= n) return;
    int beg = off[dst], end = off[dst + 1];
    float ad = ad2[dst];

    float m = -INFINITY, s = 0.f;
    float2 acc = make_float2(0.f, 0.f);

    int i = beg;
    for (; i + 4 <= end; i += 4) {
        int e0 = elist[i], e1 = elist[i + 1], e2 = elist[i + 2], e3 = elist[i + 3];
        float a0 = as2[e0], a1 = as2[e1], a2 = as2[e2], a3 = as2[e3];
        float2 y0 = *(const float2*)(h2 + (size_t)e0 * OUTC + 2 * lane);
        float2 y1 = *(const float2*)(h2 + (size_t)e1 * OUTC + 2 * lane);
        float2 y2 = *(const float2*)(h2 + (size_t)e2 * OUTC + 2 * lane);
        float2 y3 = *(const float2*)(h2 + (size_t)e3 * OUTC + 2 * lane);
        float v0 = LRELU(a0 + ad), v1 = LRELU(a1 + ad);
        float v2 = LRELU(a2 + ad), v3 = LRELU(a3 + ad);
        float bm = fmaxf(fmaxf(v0, v1), fmaxf(v2, v3));
        if (bm > m) {
            float sc = __expf(m - bm);
            s *= sc; acc.x *= sc; acc.y *= sc;
            m = bm;
        }
        float p0 = __expf(v0 - m), p1 = __expf(v1 - m);
        float p2 = __expf(v2 - m), p3 = __expf(v3 - m);
        s += (p0 + p1) + (p2 + p3);
        acc.x = fmaf(y0.x, p0, acc.x); acc.y = fmaf(y0.y, p0, acc.y);
        acc.x = fmaf(y1.x, p1, acc.x); acc.y = fmaf(y1.y, p1, acc.y);
        acc.x = fmaf(y2.x, p2, acc.x); acc.y = fmaf(y2.y, p2, acc.y);
        acc.x = fmaf(y3.x, p3, acc.x); acc.y = fmaf(y3.y, p3, acc.y);
    }
    for (; i < end; i++) {
        int e0 = elist[i];
        float a0 = as2[e0];
        float2 y0 = *(const float2*)(h2 + (size_t)e0 * OUTC + 2 * lane);
        float v0 = LRELU(a0 + ad);
        if (v0 > m) {
            float sc = __expf(m - v0);
            s *= sc; acc.x *= sc; acc.y *= sc;
            m = v0;
        }
        float p0 = __expf(v0 - m);
        s += p0;
        acc.x = fmaf(y0.x, p0, acc.x); acc.y = fmaf(y0.y, p0, acc.y);
    }

    float inv = 1.0f / (s + EPSF);
    float2 bb = *(const float2*)(b2 + 2 * lane);
    float2 o;
    o.x = fmaf(acc.x, inv, bb.x);
    o.y = fmaf(acc.y, inv, bb.y);
    *(float2*)(out + (size_t)dst * OUTC + 2 * lane) = o;
}

// ---------------- launcher ----------------
extern "C" void kernel_launch(void* const* d_in, const int* in_sizes, int n_in,
                              void* d_out, int out_size) {
    float *p_h1, *p_out1, *p_h2, *p_ws1, *p_as2, *p_ad2;
    float4 *p_s1, *p_d1;
    int *p_deg, *p_cur, *p_off, *p_elist;
    cudaGetSymbolAddress((void**)&p_h1,    g_h1);
    cudaGetSymbolAddress((void**)&p_out1,  g_out1);
    cudaGetSymbolAddress((void**)&p_h2,    g_h2);
    cudaGetSymbolAddress((void**)&p_ws1,   g_ws1);
    cudaGetSymbolAddress((void**)&p_s1,    g_s1);
    cudaGetSymbolAddress((void**)&p_d1,    g_d1);
    cudaGetSymbolAddress((void**)&p_as2,   g_as2);
    cudaGetSymbolAddress((void**)&p_ad2,   g_ad2);
    cudaGetSymbolAddress((void**)&p_deg,   g_deg);
    cudaGetSymbolAddress((void**)&p_cur,   g_cursor);
    cudaGetSymbolAddress((void**)&p_off,   g_off);
    cudaGetSymbolAddress((void**)&p_elist, g_elist);

    const float* x = nullptr; const int* ei = nullptr;
    const float* W1 = nullptr; const float* W2 = nullptr;
    const float* s192[3] = {nullptr, nullptr, nullptr}; int n192 = 0;
    const float* s64 [3] = {nullptr, nullptr, nullptr}; int n64  = 0;
    for (int i = 0; i < n_in; i++) {
        int sz = in_sizes[i];
        if      (sz == NN * INC)        x  = (const float*)d_in[i];
        else if (sz == 2 * EE)          ei = (const int*)  d_in[i];
        else if (sz == INC * H1DIM)     W1 = (const float*)d_in[i];
        else if (sz == H1DIM * OUTC)    W2 = (const float*)d_in[i];
        else if (sz == H1DIM && n192 < 3) s192[n192++] = (const float*)d_in[i];
        else if (sz == OUTC  && n64  < 3) s64 [n64++]  = (const float*)d_in[i];
    }
    const float* att_src1 = s192[0]; const float* att_dst1 = s192[1]; const float* b1 = s192[2];
    const float* att_src2 = s64[0];  const float* att_dst2 = s64[1];  const float* b2 = s64[2];

    float* out = (float*)d_out;
    int n  = NN;
    int e  = EE;
    int et = e + n;

    // Fork: CSR build on side stream, layer-1 dense compute on main stream.
    // Stream/events created once (host objects; no device memory involved).
    static cudaStream_t s2 = nullptr;
    static cudaEvent_t evFork = nullptr, evJoin = nullptr;
    if (!s2) {
        cudaStreamCreateWithFlags(&s2, cudaStreamNonBlocking);
        cudaEventCreateWithFlags(&evFork, cudaEventDisableTiming);
        cudaEventCreateWithFlags(&evJoin, cudaEventDisableTiming);
    }

    cudaEventRecord(evFork, 0);
    cudaStreamWaitEvent(s2, evFork, 0);

    // side stream: CSR
    cudaMemsetAsync(p_deg, 0, n * sizeof(int), s2);
    k_hist  <<<(et + 511) / 512, 512, 0, s2>>>(ei, p_deg, e, et);
    k_scan  <<<1, 1024, 0, s2>>>(p_deg, p_off, p_cur, n);
    k_bucket<<<(et + 511) / 512, 512, 0, s2>>>(ei, p_off, p_cur, p_elist, e, et);
    cudaEventRecord(evJoin, s2);

    // main stream: layer-1 dense
    k_wvec  <<<3, 256>>>(W1, att_src1, att_dst1, p_ws1);
    k_logits<<<(n + 7) / 8, 256>>>(x, p_ws1, p_s1, p_d1, n);
    {
        dim3 grid(H1DIM / 64, (n + 127) / 128);
        k_gemm<<<grid, 256>>>(x, W1, p_h1, n, H1DIM, INC);
    }

    // join: gat1 needs both CSR and h1/logits
    cudaStreamWaitEvent(0, evJoin, 0);
    k_gat1<<<(n + 15) / 16, 512>>>(p_elist, p_off, p_s1, p_d1, p_h1, b1, p_out1, n);

    // layer 2
    {
        dim3 grid(1, (n + 127) / 128);
        k_gemm2<<<grid, 256>>>(p_out1, W2, att_src2, att_dst2, p_h2, p_as2, p_ad2, n);
    }
    k_gat2<<<(n + 15) / 16, 512>>>(p_elist, p_off, p_as2, p_ad2, p_h2, b2, out, n);
}